// round 12
// baseline (speedup 1.0000x reference)
#include <cuda_runtime.h>
#include <cuda_bf16.h>
#include <cuda_fp16.h>
#include <math.h>
#include <stdint.h>

#define BB 8
#define NN 4096
#define CC 512
#define DD 64
#define LOG2E 1.4426950408889634f

// Scratch (allocation-free: __device__ globals)
__device__ __half g_f[BB * NN * DD];           // f16, log2e folded
__device__ __half g_g[BB * NN * DD];           // f16
__device__ __nv_bfloat16 g_h[BB * NN * DD];
__device__ __nv_bfloat16 g_Wt[3 * 64 * 512];   // [p][n][k] bf16, W transposed (Wf pre-scaled by log2e)
__device__ __nv_bfloat16 g_Wvb[64 * 512];      // Wv bf16, row-major [d][c]

static __device__ __forceinline__ unsigned pack_bf16(float a, float b) {
    __nv_bfloat162 t = __floats2bfloat162_rn(a, b);
    return *reinterpret_cast<unsigned*>(&t);
}
static __device__ __forceinline__ unsigned pack_f16(float a, float b) {
    __half2 t = __floats2half2_rn(a, b);
    return *reinterpret_cast<unsigned*>(&t);
}
static __device__ __forceinline__ unsigned smem_u32(const void* p) {
    return (unsigned)__cvta_generic_to_shared(p);
}
static __device__ __forceinline__ float ex2f(float x) {
    float y;
    asm("ex2.approx.f32 %0, %1;" : "=f"(y) : "f"(x));
    return y;
}
// non-volatile register-only mmas: ptxas may schedule freely
static __device__ __forceinline__ void mma_bf16(float* d, const unsigned* a, const unsigned* b) {
    asm("mma.sync.aligned.m16n8k16.row.col.f32.bf16.bf16.f32 "
        "{%0,%1,%2,%3},{%4,%5,%6,%7},{%8,%9},{%0,%1,%2,%3};\n"
        : "+f"(d[0]), "+f"(d[1]), "+f"(d[2]), "+f"(d[3])
        : "r"(a[0]), "r"(a[1]), "r"(a[2]), "r"(a[3]), "r"(b[0]), "r"(b[1]));
}
// f16 x f16 -> f16 accumulate (2 packed C/D regs)
static __device__ __forceinline__ void mma_f16acc(unsigned* d, const unsigned* a, const unsigned* b) {
    asm("mma.sync.aligned.m16n8k16.row.col.f16.f16.f16.f16 "
        "{%0,%1},{%2,%3,%4,%5},{%6,%7},{%0,%1};\n"
        : "+r"(d[0]), "+r"(d[1])
        : "r"(a[0]), "r"(a[1]), "r"(a[2]), "r"(a[3]), "r"(b[0]), "r"(b[1]));
}
static __device__ __forceinline__ void ldsm_x4(unsigned& r0, unsigned& r1, unsigned& r2, unsigned& r3, unsigned addr) {
    asm volatile("ldmatrix.sync.aligned.m8n8.x4.shared.b16 {%0,%1,%2,%3},[%4];\n"
                 : "=r"(r0), "=r"(r1), "=r"(r2), "=r"(r3) : "r"(addr));
}
static __device__ __forceinline__ void ldsm_x4_t(unsigned& r0, unsigned& r1, unsigned& r2, unsigned& r3, unsigned addr) {
    asm volatile("ldmatrix.sync.aligned.m8n8.x4.trans.shared.b16 {%0,%1,%2,%3},[%4];\n"
                 : "=r"(r0), "=r"(r1), "=r"(r2), "=r"(r3) : "r"(addr));
}

#define CP_ASYNC16(dst_u32, src_ptr) \
    asm volatile("cp.async.cg.shared.global [%0],[%1],16;\n" :: "r"(dst_u32), "l"(src_ptr))
#define CP_COMMIT asm volatile("cp.async.commit_group;\n" ::)
#define CP_WAIT0  asm volatile("cp.async.wait_group 0;\n" ::)
#define CP_WAIT1  asm volatile("cp.async.wait_group 1;\n" ::)

// ============================================================
// Kernel 0: weight prep
// ============================================================
__global__ __launch_bounds__(512) void prep_kernel(
    const float* __restrict__ Wf, const float* __restrict__ Wg,
    const float* __restrict__ Wh, const float* __restrict__ Wv)
{
    int idx = blockIdx.x * 512 + threadIdx.x;
    if (idx < 3 * 64 * 512) {
        int p = idx >> 15, n = (idx >> 9) & 63, k = idx & 511;
        const float* W = (p == 0) ? Wf : (p == 1) ? Wg : Wh;
        float v = W[k * 64 + n];
        if (p == 0) v *= LOG2E;
        g_Wt[idx] = __float2bfloat16(v);
    } else {
        int j = idx - 3 * 64 * 512;
        g_Wvb[j] = __float2bfloat16(Wv[j]);
    }
}

// ============================================================
// Kernel 1: projections — double-buffered; f,g emitted as f16,
// h as bf16. grid (64, 8), 384 threads.
// ============================================================
#define PX 72
__global__ __launch_bounds__(384) void proj_kernel(
    const float* __restrict__ x,
    const float* __restrict__ bfv, const float* __restrict__ bgv, const float* __restrict__ bhv)
{
    extern __shared__ __align__(16) char smem_raw[];
    __nv_bfloat16* sX = reinterpret_cast<__nv_bfloat16*>(smem_raw); // [2][64][PX]
    __nv_bfloat16* sW = sX + 2 * 64 * PX;                            // [2][3][64][PX]

    const int b   = blockIdx.y;
    const int n0  = blockIdx.x * 64;
    const int tid = threadIdx.x;
    const int lane = tid & 31, wid = tid >> 5;
    const int p  = wid >> 2;
    const int r0 = (wid & 3) * 16;
    const int l4 = lane >> 2, l2 = lane & 3;

    float acc[8][4];
#pragma unroll
    for (int i = 0; i < 8; i++)
#pragma unroll
        for (int j = 0; j < 4; j++) acc[i][j] = 0.f;

#define STAGE_X(kc, bufi)                                                           \
    for (int idx = tid; idx < 512; idx += 384) {                                    \
        int r = idx >> 3, c8 = (idx & 7) << 3;                                      \
        const float* src = x + ((size_t)b * NN + n0 + r) * CC + (kc) * 64 + c8;     \
        float4 v0 = *reinterpret_cast<const float4*>(src);                          \
        float4 v1 = *reinterpret_cast<const float4*>(src + 4);                      \
        uint4 u;                                                                    \
        u.x = pack_bf16(v0.x, v0.y); u.y = pack_bf16(v0.z, v0.w);                   \
        u.z = pack_bf16(v1.x, v1.y); u.w = pack_bf16(v1.z, v1.w);                   \
        *reinterpret_cast<uint4*>(sX + ((bufi) * 64 + r) * PX + c8) = u;            \
    }

#define STAGE_W(kc, bufi)                                                           \
    for (int idx = tid; idx < 1536; idx += 384) {                                   \
        int pp = idx >> 9, n = (idx >> 3) & 63, k8 = (idx & 7) << 3;                \
        CP_ASYNC16(smem_u32(sW + (((bufi) * 3 + pp) * 64 + n) * PX + k8),           \
                   g_Wt + ((pp * 64 + n) << 9) + (kc) * 64 + k8);                   \
    }                                                                               \
    CP_COMMIT;

    STAGE_X(0, 0);
    STAGE_W(0, 0);

    for (int kc = 0; kc < 8; kc++) {
        const int buf = kc & 1;
        if (kc < 7) {
            STAGE_X(kc + 1, buf ^ 1);
            STAGE_W(kc + 1, buf ^ 1);
            CP_WAIT1;
        } else {
            CP_WAIT0;
        }
        __syncthreads();

        const __nv_bfloat16* Xb = sX + buf * 64 * PX;
        const __nv_bfloat16* Wb = sW + (buf * 3 + p) * 64 * PX;

#pragma unroll
        for (int kt = 0; kt < 4; kt++) {
            unsigned a[4];
            ldsm_x4(a[0], a[1], a[2], a[3],
                    smem_u32(Xb + (r0 + (lane & 15)) * PX + kt * 16 + ((lane >> 4) << 3)));
#pragma unroll
            for (int nt2 = 0; nt2 < 4; nt2++) {
                unsigned b0, b1, b2, b3;
                int row = nt2 * 16 + (((lane >> 4) & 1) << 3) + (lane & 7);
                int col = kt * 16 + (((lane >> 3) & 1) << 3);
                ldsm_x4(b0, b1, b2, b3, smem_u32(Wb + row * PX + col));
                unsigned bb0[2] = {b0, b1}, bb1[2] = {b2, b3};
                mma_bf16(acc[2 * nt2], a, bb0);
                mma_bf16(acc[2 * nt2 + 1], a, bb1);
            }
        }
        __syncthreads();
    }

    if (p == 2) {
#pragma unroll
        for (int nt = 0; nt < 8; nt++) {
            int c0 = nt * 8 + l2 * 2;
            float b0 = bhv[c0], b1 = bhv[c0 + 1];
            int row = n0 + r0 + l4;
            *reinterpret_cast<unsigned*>(&g_h[((size_t)b * NN + row    ) * DD + c0]) =
                pack_bf16(acc[nt][0] + b0, acc[nt][1] + b1);
            *reinterpret_cast<unsigned*>(&g_h[((size_t)b * NN + row + 8) * DD + c0]) =
                pack_bf16(acc[nt][2] + b0, acc[nt][3] + b1);
        }
    } else {
        const float* bias = (p == 0) ? bfv : bgv;
        const float bs = (p == 0) ? LOG2E : 1.f;
        __half* dst = (p == 0) ? g_f : g_g;
#pragma unroll
        for (int nt = 0; nt < 8; nt++) {
            int c0 = nt * 8 + l2 * 2;
            float b0 = bias[c0] * bs, b1 = bias[c0 + 1] * bs;
            int row = n0 + r0 + l4;
            *reinterpret_cast<unsigned*>(&dst[((size_t)b * NN + row    ) * DD + c0]) =
                pack_f16(acc[nt][0] + b0, acc[nt][1] + b1);
            *reinterpret_cast<unsigned*>(&dst[((size_t)b * NN + row + 8) * DD + c0]) =
                pack_f16(acc[nt][2] + b0, acc[nt][3] + b1);
        }
    }
}

// ============================================================
// Kernel 2: FUSED flash attention + output projection + residual.
// Loop: S (f16-acc) / exp2 / PV (bf16). Tail: ctx -> smem, Wv staged
// into dead K/H smem, per-warp 16x512 GEMM + bv + x + store out.
// 8 warps x 16 q-rows, 256 threads, grid (32, 8).
// ============================================================
#define WVF 520
#define ISSUE_S(kb, sc, Kb)                                                          \
    do {                                                                             \
        (sc)[0] = 0u; (sc)[1] = 0u; (sc)[2] = 0u; (sc)[3] = 0u;                      \
        _Pragma("unroll")                                                            \
        for (int kt = 0; kt < 4; kt++) {                                             \
            unsigned b0, b1, b2, b3;                                                 \
            int row = (kb) * 16 + (((lane >> 4) & 1) << 3) + (lane & 7);             \
            int col = kt * 16 + (((lane >> 3) & 1) << 3);                            \
            ldsm_x4(b0, b1, b2, b3, smem_u32((Kb) + row * 72 + col));                \
            unsigned bb0[2] = {b0, b1}, bb1[2] = {b2, b3};                           \
            mma_f16acc((sc), qa[kt], bb0);                                           \
            mma_f16acc((sc) + 2, qa[kt], bb1);                                       \
        }                                                                            \
    } while (0)

__global__ __launch_bounds__(256, 2) void attn_kernel(
    const float* __restrict__ gamma_p, const float* __restrict__ x,
    const float* __restrict__ bv, float* __restrict__ out)
{
    extern __shared__ __align__(16) char smem_raw[];
    __half* sQ = reinterpret_cast<__half*>(smem_raw);                 // [128][72]
    __half* sK = sQ + 128 * 72;                                        // [2][128][72]
    __nv_bfloat16* sH = reinterpret_cast<__nv_bfloat16*>(sK + 2 * 128 * 72); // [2][128][72]
    // tail aliases (used only after the loop):
    __nv_bfloat16* sCtx = reinterpret_cast<__nv_bfloat16*>(smem_raw);          // [128][72]
    __nv_bfloat16* sWv  = reinterpret_cast<__nv_bfloat16*>(sK);                 // [64][520]

    const int b  = blockIdx.y;
    const int q0 = blockIdx.x * 128;
    const int tid = threadIdx.x, lane = tid & 31, w = tid >> 5;
    const int l4 = lane >> 2, l2 = lane & 3;
    const int r0 = w * 16;

    // stage K0 (f16) + H0 (bf16)
    for (int idx = tid; idx < 1024; idx += 256) {
        int r = (idx >> 3) & 127, c8 = (idx & 7) << 3;
        CP_ASYNC16(smem_u32(sK + r * 72 + c8), g_g + ((size_t)b * NN + r) * DD + c8);
    }
    for (int idx = tid; idx < 1024; idx += 256) {
        int r = (idx >> 3) & 127, c8 = (idx & 7) << 3;
        CP_ASYNC16(smem_u32(sH + r * 72 + c8), g_h + ((size_t)b * NN + r) * DD + c8);
    }
    CP_COMMIT;

    // Q tile
    for (int idx = tid; idx < 1024; idx += 256) {
        int r = idx >> 3, c8 = (idx & 7) << 3;
        *reinterpret_cast<uint4*>(sQ + r * 72 + c8) =
            *reinterpret_cast<const uint4*>(&g_f[((size_t)b * NN + q0 + r) * DD + c8]);
    }
    __syncthreads();

    unsigned qa[4][4];
#pragma unroll
    for (int kt = 0; kt < 4; kt++)
        ldsm_x4(qa[kt][0], qa[kt][1], qa[kt][2], qa[kt][3],
                smem_u32(sQ + (r0 + (lane & 15)) * 72 + kt * 16 + ((lane >> 4) << 3)));

    float l0 = 0.f, l1 = 0.f;
    float oacc[8][4];
#pragma unroll
    for (int i = 0; i < 8; i++)
#pragma unroll
        for (int j = 0; j < 4; j++) oacc[i][j] = 0.f;

    for (int t = 0; t < 32; t++) {
        const int buf = t & 1;
        CP_WAIT0;
        __syncthreads();

        if (t + 1 < 32) {
            int nb = (t + 1) & 1;
            for (int idx = tid; idx < 1024; idx += 256) {
                int r = (idx >> 3) & 127, c8 = (idx & 7) << 3;
                CP_ASYNC16(smem_u32(sK + (nb * 128 + r) * 72 + c8),
                           g_g + ((size_t)b * NN + (t + 1) * 128 + r) * DD + c8);
            }
            for (int idx = tid; idx < 1024; idx += 256) {
                int r = (idx >> 3) & 127, c8 = (idx & 7) << 3;
                CP_ASYNC16(smem_u32(sH + (nb * 128 + r) * 72 + c8),
                           g_h + ((size_t)b * NN + (t + 1) * 128 + r) * DD + c8);
            }
            CP_COMMIT;
        }

        const __half* Kb = sK + buf * 128 * 72;
        const __nv_bfloat16* Hb = sH + buf * 128 * 72;

        unsigned scA[4], scB[4];
        ISSUE_S(0, scA, Kb);

#pragma unroll
        for (int kb = 0; kb < 8; kb++) {
            unsigned* cur = (kb & 1) ? scB : scA;
            unsigned* nxt = (kb & 1) ? scA : scB;

            if (kb < 7) ISSUE_S(kb + 1, nxt, Kb);

            unsigned hb[4][4];
#pragma unroll
            for (int nt2 = 0; nt2 < 4; nt2++) {
                int row = kb * 16 + (((lane >> 3) & 1) << 3) + (lane & 7);
                int col = nt2 * 16 + ((lane >> 4) << 3);
                ldsm_x4_t(hb[nt2][0], hb[nt2][1], hb[nt2][2], hb[nt2][3],
                          smem_u32(Hb + row * 72 + col));
            }

            float2 f01 = __half22float2(*reinterpret_cast<__half2*>(&cur[0]));
            float2 f23 = __half22float2(*reinterpret_cast<__half2*>(&cur[1]));
            float2 f45 = __half22float2(*reinterpret_cast<__half2*>(&cur[2]));
            float2 f67 = __half22float2(*reinterpret_cast<__half2*>(&cur[3]));
            float e0 = ex2f(f01.x), e1 = ex2f(f01.y);
            float e2 = ex2f(f23.x), e3 = ex2f(f23.y);
            float e4 = ex2f(f45.x), e5 = ex2f(f45.y);
            float e6 = ex2f(f67.x), e7 = ex2f(f67.y);
            l0 += e0 + e1 + e4 + e5;
            l1 += e2 + e3 + e6 + e7;

            unsigned pa[4];
            pa[0] = pack_bf16(e0, e1);
            pa[1] = pack_bf16(e2, e3);
            pa[2] = pack_bf16(e4, e5);
            pa[3] = pack_bf16(e6, e7);

#pragma unroll
            for (int nt2 = 0; nt2 < 4; nt2++) {
                unsigned bb0[2] = {hb[nt2][0], hb[nt2][1]};
                unsigned bb1[2] = {hb[nt2][2], hb[nt2][3]};
                mma_bf16(oacc[2 * nt2], pa, bb0);
                mma_bf16(oacc[2 * nt2 + 1], pa, bb1);
            }
        }
    }

    l0 += __shfl_xor_sync(0xffffffffu, l0, 1);
    l0 += __shfl_xor_sync(0xffffffffu, l0, 2);
    l1 += __shfl_xor_sync(0xffffffffu, l1, 1);
    l1 += __shfl_xor_sync(0xffffffffu, l1, 2);

    float gm = *gamma_p;
    float s0 = gm / l0, s1 = gm / l1;

    // ---- fused epilogue ----
    // stage Wv (64x512 bf16) into dead K/H smem, async
    for (int idx = tid; idx < 4096; idx += 256) {
        int r = idx >> 6, c8 = (idx & 63) << 3;
        CP_ASYNC16(smem_u32(sWv + r * WVF + c8), g_Wvb + (r << 9) + c8);
    }
    CP_COMMIT;

    // scaled ctx (bf16) into sQ region (qa regs already consumed; sQ dead)
#pragma unroll
    for (int nt = 0; nt < 8; nt++) {
        int c0 = nt * 8 + l2 * 2;
        *reinterpret_cast<unsigned*>(sCtx + (r0 + l4    ) * 72 + c0) =
            pack_bf16(oacc[nt][0] * s0, oacc[nt][1] * s0);
        *reinterpret_cast<unsigned*>(sCtx + (r0 + l4 + 8) * 72 + c0) =
            pack_bf16(oacc[nt][2] * s1, oacc[nt][3] * s1);
    }
    CP_WAIT0;
    __syncthreads();

    // A fragments for this warp's 16 ctx rows (K=64 -> 4 kt)
    unsigned ca[4][4];
#pragma unroll
    for (int kt = 0; kt < 4; kt++)
        ldsm_x4(ca[kt][0], ca[kt][1], ca[kt][2], ca[kt][3],
                smem_u32(sCtx + (r0 + (lane & 15)) * 72 + kt * 16 + ((lane >> 4) << 3)));

    // out[q0+r0 .. +15][0..511] = ctx @ Wv + bv + x, in 4 chunks of 128 cols
#pragma unroll
    for (int ch = 0; ch < 4; ch++) {
        float acc[16][4];
#pragma unroll
        for (int i = 0; i < 16; i++)
#pragma unroll
            for (int j = 0; j < 4; j++) acc[i][j] = 0.f;

#pragma unroll
        for (int kt = 0; kt < 4; kt++) {
#pragma unroll
            for (int nt2 = 0; nt2 < 8; nt2++) {
                unsigned b0, b1, b2, b3;
                int row = kt * 16 + (((lane >> 3) & 1) << 3) + (lane & 7);
                int col = ch * 128 + nt2 * 16 + ((lane >> 4) << 3);
                ldsm_x4_t(b0, b1, b2, b3, smem_u32(sWv + row * WVF + col));
                unsigned bb0[2] = {b0, b1}, bb1[2] = {b2, b3};
                mma_bf16(acc[2 * nt2], ca[kt], bb0);
                mma_bf16(acc[2 * nt2 + 1], ca[kt], bb1);
            }
        }

#pragma unroll
        for (int nt = 0; nt < 16; nt++) {
            int col = ch * 128 + nt * 8 + l2 * 2;
            float2 bvv = *reinterpret_cast<const float2*>(&bv[col]);
            size_t off0 = ((size_t)b * NN + q0 + r0 + l4    ) * CC + col;
            size_t off1 = ((size_t)b * NN + q0 + r0 + l4 + 8) * CC + col;
            float2 x0 = *reinterpret_cast<const float2*>(&x[off0]);
            float2 x1 = *reinterpret_cast<const float2*>(&x[off1]);
            float2 o0 = make_float2(acc[nt][0] + bvv.x + x0.x, acc[nt][1] + bvv.y + x0.y);
            float2 o1 = make_float2(acc[nt][2] + bvv.x + x1.x, acc[nt][3] + bvv.y + x1.y);
            *reinterpret_cast<float2*>(&out[off0]) = o0;
            *reinterpret_cast<float2*>(&out[off1]) = o1;
        }
    }
}

// ============================================================
extern "C" void kernel_launch(void* const* d_in, const int* in_sizes, int n_in,
                              void* d_out, int out_size)
{
    const float* x     = (const float*)d_in[0];
    const float* Wf    = (const float*)d_in[1];
    const float* bf    = (const float*)d_in[2];
    const float* Wg    = (const float*)d_in[3];
    const float* bg    = (const float*)d_in[4];
    const float* Wh    = (const float*)d_in[5];
    const float* bh    = (const float*)d_in[6];
    const float* Wv    = (const float*)d_in[7];
    const float* bv    = (const float*)d_in[8];
    const float* gamma = (const float*)d_in[9];
    float* out = (float*)d_out;

    const int proj_smem = (2 * 64 * PX + 2 * 3 * 64 * PX) * 2;          // 73728
    const int attn_smem = (128 * 72 + 2 * 128 * 72 + 2 * 128 * 72) * 2; // 92160
    cudaFuncSetAttribute(proj_kernel, cudaFuncAttributeMaxDynamicSharedMemorySize, proj_smem);
    cudaFuncSetAttribute(attn_kernel, cudaFuncAttributeMaxDynamicSharedMemorySize, attn_smem);

    prep_kernel<<<256, 512>>>(Wf, Wg, Wh, Wv);
    proj_kernel<<<dim3(NN / 64, BB), 384, proj_smem>>>(x, bf, bg, bh);
    attn_kernel<<<dim3(NN / 128, BB), 256, attn_smem>>>(gamma, x, bv, out);
}

// round 13
// speedup vs baseline: 1.0815x; 1.0815x over previous
#include <cuda_runtime.h>
#include <cuda_bf16.h>
#include <cuda_fp16.h>
#include <math.h>
#include <stdint.h>

#define BB 8
#define NN 4096
#define CC 512
#define DD 64
#define LOG2E 1.4426950408889634f

// Scratch (allocation-free: __device__ globals)
__device__ __half g_f[BB * NN * DD];           // f16, log2e folded
__device__ __half g_g[BB * NN * DD];           // f16
__device__ __nv_bfloat16 g_h[BB * NN * DD];
__device__ __nv_bfloat16 g_ctx[BB * NN * DD];
__device__ __nv_bfloat16 g_Wt[3 * 64 * 512];   // [p][n][k] bf16, W transposed (Wf pre-scaled by log2e)
__device__ __nv_bfloat16 g_Wvb[64 * 512];      // Wv bf16, row-major [d][c]

static __device__ __forceinline__ unsigned pack_bf16(float a, float b) {
    __nv_bfloat162 t = __floats2bfloat162_rn(a, b);
    return *reinterpret_cast<unsigned*>(&t);
}
static __device__ __forceinline__ unsigned pack_f16(float a, float b) {
    __half2 t = __floats2half2_rn(a, b);
    return *reinterpret_cast<unsigned*>(&t);
}
static __device__ __forceinline__ unsigned smem_u32(const void* p) {
    return (unsigned)__cvta_generic_to_shared(p);
}
static __device__ __forceinline__ float ex2f(float x) {
    float y;
    asm("ex2.approx.f32 %0, %1;" : "=f"(y) : "f"(x));
    return y;
}
// non-volatile register-only mmas: ptxas may schedule freely
static __device__ __forceinline__ void mma_bf16(float* d, const unsigned* a, const unsigned* b) {
    asm("mma.sync.aligned.m16n8k16.row.col.f32.bf16.bf16.f32 "
        "{%0,%1,%2,%3},{%4,%5,%6,%7},{%8,%9},{%0,%1,%2,%3};\n"
        : "+f"(d[0]), "+f"(d[1]), "+f"(d[2]), "+f"(d[3])
        : "r"(a[0]), "r"(a[1]), "r"(a[2]), "r"(a[3]), "r"(b[0]), "r"(b[1]));
}
// f16 x f16 -> f16 accumulate (2 packed C/D regs)
static __device__ __forceinline__ void mma_f16acc(unsigned* d, const unsigned* a, const unsigned* b) {
    asm("mma.sync.aligned.m16n8k16.row.col.f16.f16.f16.f16 "
        "{%0,%1},{%2,%3,%4,%5},{%6,%7},{%0,%1};\n"
        : "+r"(d[0]), "+r"(d[1])
        : "r"(a[0]), "r"(a[1]), "r"(a[2]), "r"(a[3]), "r"(b[0]), "r"(b[1]));
}
static __device__ __forceinline__ void ldsm_x4(unsigned& r0, unsigned& r1, unsigned& r2, unsigned& r3, unsigned addr) {
    asm volatile("ldmatrix.sync.aligned.m8n8.x4.shared.b16 {%0,%1,%2,%3},[%4];\n"
                 : "=r"(r0), "=r"(r1), "=r"(r2), "=r"(r3) : "r"(addr));
}
static __device__ __forceinline__ void ldsm_x4_t(unsigned& r0, unsigned& r1, unsigned& r2, unsigned& r3, unsigned addr) {
    asm volatile("ldmatrix.sync.aligned.m8n8.x4.trans.shared.b16 {%0,%1,%2,%3},[%4];\n"
                 : "=r"(r0), "=r"(r1), "=r"(r2), "=r"(r3) : "r"(addr));
}

#define CP_ASYNC16(dst_u32, src_ptr) \
    asm volatile("cp.async.cg.shared.global [%0],[%1],16;\n" :: "r"(dst_u32), "l"(src_ptr))
#define CP_COMMIT asm volatile("cp.async.commit_group;\n" ::)
#define CP_WAIT0  asm volatile("cp.async.wait_group 0;\n" ::)
#define CP_WAIT1  asm volatile("cp.async.wait_group 1;\n" ::)

// ============================================================
// Kernel 0: weight prep
// ============================================================
__global__ __launch_bounds__(512) void prep_kernel(
    const float* __restrict__ Wf, const float* __restrict__ Wg,
    const float* __restrict__ Wh, const float* __restrict__ Wv)
{
    int idx = blockIdx.x * 512 + threadIdx.x;
    if (idx < 3 * 64 * 512) {
        int p = idx >> 15, n = (idx >> 9) & 63, k = idx & 511;
        const float* W = (p == 0) ? Wf : (p == 1) ? Wg : Wh;
        float v = W[k * 64 + n];
        if (p == 0) v *= LOG2E;
        g_Wt[idx] = __float2bfloat16(v);
    } else {
        int j = idx - 3 * 64 * 512;
        g_Wvb[j] = __float2bfloat16(Wv[j]);
    }
}

// ============================================================
// Kernel 1: projections — double-buffered; f,g emitted as f16,
// h as bf16. grid (64, 8), 384 threads.
// ============================================================
#define PX 72
__global__ __launch_bounds__(384) void proj_kernel(
    const float* __restrict__ x,
    const float* __restrict__ bfv, const float* __restrict__ bgv, const float* __restrict__ bhv)
{
    extern __shared__ __align__(16) char smem_raw[];
    __nv_bfloat16* sX = reinterpret_cast<__nv_bfloat16*>(smem_raw); // [2][64][PX]
    __nv_bfloat16* sW = sX + 2 * 64 * PX;                            // [2][3][64][PX]

    const int b   = blockIdx.y;
    const int n0  = blockIdx.x * 64;
    const int tid = threadIdx.x;
    const int lane = tid & 31, wid = tid >> 5;
    const int p  = wid >> 2;
    const int r0 = (wid & 3) * 16;
    const int l4 = lane >> 2, l2 = lane & 3;

    float acc[8][4];
#pragma unroll
    for (int i = 0; i < 8; i++)
#pragma unroll
        for (int j = 0; j < 4; j++) acc[i][j] = 0.f;

#define STAGE_X(kc, bufi)                                                           \
    for (int idx = tid; idx < 512; idx += 384) {                                    \
        int r = idx >> 3, c8 = (idx & 7) << 3;                                      \
        const float* src = x + ((size_t)b * NN + n0 + r) * CC + (kc) * 64 + c8;     \
        float4 v0 = *reinterpret_cast<const float4*>(src);                          \
        float4 v1 = *reinterpret_cast<const float4*>(src + 4);                      \
        uint4 u;                                                                    \
        u.x = pack_bf16(v0.x, v0.y); u.y = pack_bf16(v0.z, v0.w);                   \
        u.z = pack_bf16(v1.x, v1.y); u.w = pack_bf16(v1.z, v1.w);                   \
        *reinterpret_cast<uint4*>(sX + ((bufi) * 64 + r) * PX + c8) = u;            \
    }

#define STAGE_W(kc, bufi)                                                           \
    for (int idx = tid; idx < 1536; idx += 384) {                                   \
        int pp = idx >> 9, n = (idx >> 3) & 63, k8 = (idx & 7) << 3;                \
        CP_ASYNC16(smem_u32(sW + (((bufi) * 3 + pp) * 64 + n) * PX + k8),           \
                   g_Wt + ((pp * 64 + n) << 9) + (kc) * 64 + k8);                   \
    }                                                                               \
    CP_COMMIT;

    STAGE_X(0, 0);
    STAGE_W(0, 0);

    for (int kc = 0; kc < 8; kc++) {
        const int buf = kc & 1;
        if (kc < 7) {
            STAGE_X(kc + 1, buf ^ 1);
            STAGE_W(kc + 1, buf ^ 1);
            CP_WAIT1;
        } else {
            CP_WAIT0;
        }
        __syncthreads();

        const __nv_bfloat16* Xb = sX + buf * 64 * PX;
        const __nv_bfloat16* Wb = sW + (buf * 3 + p) * 64 * PX;

#pragma unroll
        for (int kt = 0; kt < 4; kt++) {
            unsigned a[4];
            ldsm_x4(a[0], a[1], a[2], a[3],
                    smem_u32(Xb + (r0 + (lane & 15)) * PX + kt * 16 + ((lane >> 4) << 3)));
#pragma unroll
            for (int nt2 = 0; nt2 < 4; nt2++) {
                unsigned b0, b1, b2, b3;
                int row = nt2 * 16 + (((lane >> 4) & 1) << 3) + (lane & 7);
                int col = kt * 16 + (((lane >> 3) & 1) << 3);
                ldsm_x4(b0, b1, b2, b3, smem_u32(Wb + row * PX + col));
                unsigned bb0[2] = {b0, b1}, bb1[2] = {b2, b3};
                mma_bf16(acc[2 * nt2], a, bb0);
                mma_bf16(acc[2 * nt2 + 1], a, bb1);
            }
        }
        __syncthreads();
    }

    if (p == 2) {
#pragma unroll
        for (int nt = 0; nt < 8; nt++) {
            int c0 = nt * 8 + l2 * 2;
            float b0 = bhv[c0], b1 = bhv[c0 + 1];
            int row = n0 + r0 + l4;
            *reinterpret_cast<unsigned*>(&g_h[((size_t)b * NN + row    ) * DD + c0]) =
                pack_bf16(acc[nt][0] + b0, acc[nt][1] + b1);
            *reinterpret_cast<unsigned*>(&g_h[((size_t)b * NN + row + 8) * DD + c0]) =
                pack_bf16(acc[nt][2] + b0, acc[nt][3] + b1);
        }
    } else {
        const float* bias = (p == 0) ? bfv : bgv;
        const float bs = (p == 0) ? LOG2E : 1.f;
        __half* dst = (p == 0) ? g_f : g_g;
#pragma unroll
        for (int nt = 0; nt < 8; nt++) {
            int c0 = nt * 8 + l2 * 2;
            float b0 = bias[c0] * bs, b1 = bias[c0 + 1] * bs;
            int row = n0 + r0 + l4;
            *reinterpret_cast<unsigned*>(&dst[((size_t)b * NN + row    ) * DD + c0]) =
                pack_f16(acc[nt][0] + b0, acc[nt][1] + b1);
            *reinterpret_cast<unsigned*>(&dst[((size_t)b * NN + row + 8) * DD + c0]) =
                pack_f16(acc[nt][2] + b0, acc[nt][3] + b1);
        }
    }
}

// ============================================================
// Kernel 2: flash attention (R11 exact) — S-GEMM f16-acc, PV bf16-f32,
// no max, exp2 path. 8 warps x 16 q-rows, 256 threads, grid (32, 8).
// ============================================================
#define ISSUE_S(kb, sc, Kb)                                                          \
    do {                                                                             \
        (sc)[0] = 0u; (sc)[1] = 0u; (sc)[2] = 0u; (sc)[3] = 0u;                      \
        _Pragma("unroll")                                                            \
        for (int kt = 0; kt < 4; kt++) {                                             \
            unsigned b0, b1, b2, b3;                                                 \
            int row = (kb) * 16 + (((lane >> 4) & 1) << 3) + (lane & 7);             \
            int col = kt * 16 + (((lane >> 3) & 1) << 3);                            \
            ldsm_x4(b0, b1, b2, b3, smem_u32((Kb) + row * 72 + col));                \
            unsigned bb0[2] = {b0, b1}, bb1[2] = {b2, b3};                           \
            mma_f16acc((sc), qa[kt], bb0);                                           \
            mma_f16acc((sc) + 2, qa[kt], bb1);                                       \
        }                                                                            \
    } while (0)

__global__ __launch_bounds__(256, 2) void attn_kernel(const float* __restrict__ gamma_p)
{
    extern __shared__ __align__(16) char smem_raw[];
    __half* sQ = reinterpret_cast<__half*>(smem_raw);                 // [128][72]
    __half* sK = sQ + 128 * 72;                                        // [2][128][72]
    __nv_bfloat16* sH = reinterpret_cast<__nv_bfloat16*>(sK + 2 * 128 * 72); // [2][128][72]

    const int b  = blockIdx.y;
    const int q0 = blockIdx.x * 128;
    const int tid = threadIdx.x, lane = tid & 31, w = tid >> 5;
    const int l4 = lane >> 2, l2 = lane & 3;
    const int r0 = w * 16;

    for (int idx = tid; idx < 1024; idx += 256) {
        int r = (idx >> 3) & 127, c8 = (idx & 7) << 3;
        CP_ASYNC16(smem_u32(sK + r * 72 + c8), g_g + ((size_t)b * NN + r) * DD + c8);
    }
    for (int idx = tid; idx < 1024; idx += 256) {
        int r = (idx >> 3) & 127, c8 = (idx & 7) << 3;
        CP_ASYNC16(smem_u32(sH + r * 72 + c8), g_h + ((size_t)b * NN + r) * DD + c8);
    }
    CP_COMMIT;

    for (int idx = tid; idx < 1024; idx += 256) {
        int r = idx >> 3, c8 = (idx & 7) << 3;
        *reinterpret_cast<uint4*>(sQ + r * 72 + c8) =
            *reinterpret_cast<const uint4*>(&g_f[((size_t)b * NN + q0 + r) * DD + c8]);
    }
    __syncthreads();

    unsigned qa[4][4];
#pragma unroll
    for (int kt = 0; kt < 4; kt++)
        ldsm_x4(qa[kt][0], qa[kt][1], qa[kt][2], qa[kt][3],
                smem_u32(sQ + (r0 + (lane & 15)) * 72 + kt * 16 + ((lane >> 4) << 3)));

    float l0 = 0.f, l1 = 0.f;
    float oacc[8][4];
#pragma unroll
    for (int i = 0; i < 8; i++)
#pragma unroll
        for (int j = 0; j < 4; j++) oacc[i][j] = 0.f;

    for (int t = 0; t < 32; t++) {
        const int buf = t & 1;
        CP_WAIT0;
        __syncthreads();

        if (t + 1 < 32) {
            int nb = (t + 1) & 1;
            for (int idx = tid; idx < 1024; idx += 256) {
                int r = (idx >> 3) & 127, c8 = (idx & 7) << 3;
                CP_ASYNC16(smem_u32(sK + (nb * 128 + r) * 72 + c8),
                           g_g + ((size_t)b * NN + (t + 1) * 128 + r) * DD + c8);
            }
            for (int idx = tid; idx < 1024; idx += 256) {
                int r = (idx >> 3) & 127, c8 = (idx & 7) << 3;
                CP_ASYNC16(smem_u32(sH + (nb * 128 + r) * 72 + c8),
                           g_h + ((size_t)b * NN + (t + 1) * 128 + r) * DD + c8);
            }
            CP_COMMIT;
        }

        const __half* Kb = sK + buf * 128 * 72;
        const __nv_bfloat16* Hb = sH + buf * 128 * 72;

        unsigned scA[4], scB[4];
        ISSUE_S(0, scA, Kb);

#pragma unroll
        for (int kb = 0; kb < 8; kb++) {
            unsigned* cur = (kb & 1) ? scB : scA;
            unsigned* nxt = (kb & 1) ? scA : scB;

            if (kb < 7) ISSUE_S(kb + 1, nxt, Kb);

            unsigned hb[4][4];
#pragma unroll
            for (int nt2 = 0; nt2 < 4; nt2++) {
                int row = kb * 16 + (((lane >> 3) & 1) << 3) + (lane & 7);
                int col = nt2 * 16 + ((lane >> 4) << 3);
                ldsm_x4_t(hb[nt2][0], hb[nt2][1], hb[nt2][2], hb[nt2][3],
                          smem_u32(Hb + row * 72 + col));
            }

            float2 f01 = __half22float2(*reinterpret_cast<__half2*>(&cur[0]));
            float2 f23 = __half22float2(*reinterpret_cast<__half2*>(&cur[1]));
            float2 f45 = __half22float2(*reinterpret_cast<__half2*>(&cur[2]));
            float2 f67 = __half22float2(*reinterpret_cast<__half2*>(&cur[3]));
            float e0 = ex2f(f01.x), e1 = ex2f(f01.y);
            float e2 = ex2f(f23.x), e3 = ex2f(f23.y);
            float e4 = ex2f(f45.x), e5 = ex2f(f45.y);
            float e6 = ex2f(f67.x), e7 = ex2f(f67.y);
            l0 += e0 + e1 + e4 + e5;
            l1 += e2 + e3 + e6 + e7;

            unsigned pa[4];
            pa[0] = pack_bf16(e0, e1);
            pa[1] = pack_bf16(e2, e3);
            pa[2] = pack_bf16(e4, e5);
            pa[3] = pack_bf16(e6, e7);

#pragma unroll
            for (int nt2 = 0; nt2 < 4; nt2++) {
                unsigned bb0[2] = {hb[nt2][0], hb[nt2][1]};
                unsigned bb1[2] = {hb[nt2][2], hb[nt2][3]};
                mma_bf16(oacc[2 * nt2], pa, bb0);
                mma_bf16(oacc[2 * nt2 + 1], pa, bb1);
            }
        }
    }

    l0 += __shfl_xor_sync(0xffffffffu, l0, 1);
    l0 += __shfl_xor_sync(0xffffffffu, l0, 2);
    l1 += __shfl_xor_sync(0xffffffffu, l1, 1);
    l1 += __shfl_xor_sync(0xffffffffu, l1, 2);

    float gm = *gamma_p;
    float s0 = gm / l0, s1 = gm / l1;
#pragma unroll
    for (int nt = 0; nt < 8; nt++) {
        int c0 = nt * 8 + l2 * 2;
        int row = q0 + r0 + l4;
        *reinterpret_cast<unsigned*>(&g_ctx[((size_t)b * NN + row    ) * DD + c0]) =
            pack_bf16(oacc[nt][0] * s0, oacc[nt][1] * s0);
        *reinterpret_cast<unsigned*>(&g_ctx[((size_t)b * NN + row + 8) * DD + c0]) =
            pack_bf16(oacc[nt][2] * s1, oacc[nt][3] * s1);
    }
}

// ============================================================
// Kernel 3: out = ctx @ Wv + bv + x — 128-col chunks, 4 CTAs/SM.
// grid (64, 4, 8), 256 threads = 8 warps: rows (w&3)*16, cols (w>>2)*64.
// ============================================================
#define WVP 136
__global__ __launch_bounds__(256, 4) void epi_kernel(
    const float* __restrict__ x,
    const float* __restrict__ bv, float* __restrict__ out)
{
    extern __shared__ __align__(16) char smem_raw[];
    __nv_bfloat16* sCtx = reinterpret_cast<__nv_bfloat16*>(smem_raw);   // [64][72]
    __nv_bfloat16* sWv  = sCtx + 64 * 72;                                // [64][136]

    const int b    = blockIdx.z;
    const int n0   = blockIdx.x * 64;
    const int ch0  = blockIdx.y * 128;
    const int tid = threadIdx.x, lane = tid & 31, w = tid >> 5;
    const int l4 = lane >> 2, l2 = lane & 3;
    const int r0 = (w & 3) * 16;
    const int c0 = (w >> 2) * 64;

    // stage Wv slice [64][128] bf16: 1024 x 16B
    for (int idx = tid; idx < 1024; idx += 256) {
        int r = idx >> 4, c8 = (idx & 15) << 3;
        CP_ASYNC16(smem_u32(sWv + r * WVP + c8), g_Wvb + (r << 9) + ch0 + c8);
    }
    // stage ctx tile [64][64] bf16: 512 x 16B
    for (int idx = tid; idx < 512; idx += 256) {
        int r = idx >> 3, c8 = (idx & 7) << 3;
        CP_ASYNC16(smem_u32(sCtx + r * 72 + c8), &g_ctx[((size_t)b * NN + n0 + r) * DD + c8]);
    }
    CP_COMMIT;
    CP_WAIT0;
    __syncthreads();

    float acc[8][4];
#pragma unroll
    for (int i = 0; i < 8; i++)
#pragma unroll
        for (int j = 0; j < 4; j++) acc[i][j] = 0.f;

#pragma unroll
    for (int kt = 0; kt < 4; kt++) {
        unsigned a[4];
        ldsm_x4(a[0], a[1], a[2], a[3],
                smem_u32(sCtx + (r0 + (lane & 15)) * 72 + kt * 16 + ((lane >> 4) << 3)));
#pragma unroll
        for (int nt2 = 0; nt2 < 4; nt2++) {
            unsigned b0, b1, b2, b3;
            int row = kt * 16 + (((lane >> 3) & 1) << 3) + (lane & 7);
            int col = c0 + nt2 * 16 + ((lane >> 4) << 3);
            ldsm_x4_t(b0, b1, b2, b3, smem_u32(sWv + row * WVP + col));
            unsigned bb0[2] = {b0, b1}, bb1[2] = {b2, b3};
            mma_bf16(acc[2 * nt2], a, bb0);
            mma_bf16(acc[2 * nt2 + 1], a, bb1);
        }
    }

#pragma unroll
    for (int nt = 0; nt < 8; nt++) {
        int col = ch0 + c0 + nt * 8 + l2 * 2;
        float2 bvv = *reinterpret_cast<const float2*>(&bv[col]);
        size_t off0 = ((size_t)b * NN + n0 + r0 + l4    ) * CC + col;
        size_t off1 = ((size_t)b * NN + n0 + r0 + l4 + 8) * CC + col;
        float2 x0 = *reinterpret_cast<const float2*>(&x[off0]);
        float2 x1 = *reinterpret_cast<const float2*>(&x[off1]);
        float2 o0 = make_float2(acc[nt][0] + bvv.x + x0.x, acc[nt][1] + bvv.y + x0.y);
        float2 o1 = make_float2(acc[nt][2] + bvv.x + x1.x, acc[nt][3] + bvv.y + x1.y);
        *reinterpret_cast<float2*>(&out[off0]) = o0;
        *reinterpret_cast<float2*>(&out[off1]) = o1;
    }
}

// ============================================================
extern "C" void kernel_launch(void* const* d_in, const int* in_sizes, int n_in,
                              void* d_out, int out_size)
{
    const float* x     = (const float*)d_in[0];
    const float* Wf    = (const float*)d_in[1];
    const float* bf    = (const float*)d_in[2];
    const float* Wg    = (const float*)d_in[3];
    const float* bg    = (const float*)d_in[4];
    const float* Wh    = (const float*)d_in[5];
    const float* bh    = (const float*)d_in[6];
    const float* Wv    = (const float*)d_in[7];
    const float* bv    = (const float*)d_in[8];
    const float* gamma = (const float*)d_in[9];
    float* out = (float*)d_out;

    const int proj_smem = (2 * 64 * PX + 2 * 3 * 64 * PX) * 2;          // 73728
    const int attn_smem = (128 * 72 + 2 * 128 * 72 + 2 * 128 * 72) * 2; // 92160
    const int epi_smem  = (64 * 72 + 64 * WVP) * 2;                     // 26624
    cudaFuncSetAttribute(proj_kernel, cudaFuncAttributeMaxDynamicSharedMemorySize, proj_smem);
    cudaFuncSetAttribute(attn_kernel, cudaFuncAttributeMaxDynamicSharedMemorySize, attn_smem);
    cudaFuncSetAttribute(epi_kernel,  cudaFuncAttributeMaxDynamicSharedMemorySize, epi_smem);

    prep_kernel<<<256, 512>>>(Wf, Wg, Wh, Wv);
    proj_kernel<<<dim3(NN / 64, BB), 384, proj_smem>>>(x, bf, bg, bh);
    attn_kernel<<<dim3(NN / 128, BB), 256, attn_smem>>>(gamma);
    epi_kernel<<<dim3(NN / 64, 4, BB), 256, epi_smem>>>(x, bv, out);
}